// round 1
// baseline (speedup 1.0000x reference)
#include <cuda_runtime.h>
#include <cuda_bf16.h>

// y[t, f] = x[t, f] * w[f] + b[f]
// x: [8192, 4096] f32, w: [4096] f32, b: [4096] f32, out: [8192, 4096] f32.
// Pure HBM-bound elementwise: 128 MiB in + 128 MiB out. Strategy: float4
// vectorization, direct mapping, w/b served from L2 (16 KiB each).

#define TOKENS      8192
#define IN_FEATURES 4096
#define COLS4       (IN_FEATURES / 4)   // 1024, power of two
#define N4          (TOKENS * COLS4)    // 8,388,608 float4 quads

__global__ __launch_bounds__(256) void one_to_one_kernel(
    const float4* __restrict__ x,
    const float4* __restrict__ w,
    const float4* __restrict__ b,
    float4* __restrict__ out)
{
    int i = blockIdx.x * blockDim.x + threadIdx.x;
    if (i >= N4) return;

    int c = i & (COLS4 - 1);   // column quad index within the row

    float4 xv = x[i];
    float4 wv = __ldg(&w[c]);
    float4 bv = __ldg(&b[c]);

    float4 r;
    r.x = fmaf(xv.x, wv.x, bv.x);
    r.y = fmaf(xv.y, wv.y, bv.y);
    r.z = fmaf(xv.z, wv.z, bv.z);
    r.w = fmaf(xv.w, wv.w, bv.w);

    out[i] = r;
}

extern "C" void kernel_launch(void* const* d_in, const int* in_sizes, int n_in,
                              void* d_out, int out_size)
{
    const float4* x = (const float4*)d_in[0];
    const float4* w = (const float4*)d_in[1];
    const float4* b = (const float4*)d_in[2];
    float4* out = (float4*)d_out;

    const int threads = 256;
    const int blocks  = (N4 + threads - 1) / threads;  // 32768
    one_to_one_kernel<<<blocks, threads>>>(x, w, b, out);
}